// round 14
// baseline (speedup 1.0000x reference)
#include <cuda_runtime.h>
#include <cstddef>

// Shapes fixed by the problem definition.
#define BB 32
#define FF 128
#define TT 8192

// Precomputed y-pixel coordinate per output time index j (clamped to [0,127]).
// 32 KB — L2-resident and L1-hot in the main kernel.
__device__ __align__(16) float g_yp[TT];

// ---------------------------------------------------------------------------
// Kernel 1: ypix table. Each thread reads the src/dst scalars (L2 broadcast)
// and computes one j with math faithful to the JAX fp32 reference.
// ---------------------------------------------------------------------------
__global__ void __launch_bounds__(256) k_tab(const int* __restrict__ src_p,
                                             const int* __restrict__ dst_p) {
    int j = blockIdx.x * 256 + threadIdx.x;
    if (j >= TT) return;
    float sf = (float)(*src_p);
    float df = (float)(*dst_p);
    float lr = __fdiv_rn(df, sf);                                 // dest/source
    float rr = __fdiv_rn((float)TT - df, (float)TT - sf);         // (T-dest)/(T-source)

    float t   = (float)j;
    float ind = (t < df) ? __fdiv_rn(t, lr)
                         : (sf + __fdiv_rn(t - df, rr));
    ind = fminf(fmaxf(ind, 0.0f), (float)(TT - 1));

    float yp = __fdiv_rn(ind, (float)(TT - 1)) * (float)(FF - 1);
    yp = fminf(fmaxf(yp, 0.0f), (float)(FF - 1));
    g_yp[j] = yp;
}

// ---------------------------------------------------------------------------
// Kernel 2 (fused): one block per (b,i) output row, 256 threads.
//
// Prologue: gather input columns x0(i), x1(i) across 128 freq rows (256
// parallel scattered LDGs — x1=x0+1 so both usually share a 32B sector),
// build the x-lerped column A and forward diff D interleaved as
// float2 sAD[r] = {A[r], A[r+1]-A[r]} (D[127]=0 absorbs the y1 clamp).
//
// Main loop: 8 x float4 per thread. ypix comes from the 32KB table via one
// LDG.128 per 4 outputs; per element only floor/cvt/sub remain. The 4
// consecutive j's almost always share y0 -> 1 broadcast LDS.64 + 3 predicated
// (mostly inactive) fetches. out[j] = fma(wy, D[y0], A[y0]); streamed stores.
// ---------------------------------------------------------------------------
__global__ void __launch_bounds__(256) k_fused(const float* __restrict__ S,
                                               float* __restrict__ out) {
    __shared__ float2 sAD[FF];
    __shared__ float  sTmp[FF];

    int row = blockIdx.x;            // b*128 + i
    int tid = threadIdx.x;
    int i   = row & (FF - 1);
    int b   = row >> 7;

    // x_pix = i/(F-1)*(T-1), clip, floor — faithful fp32 math.
    float xpix = __fdiv_rn((float)i, (float)(FF - 1)) * (float)(TT - 1);
    xpix = fminf(fmaxf(xpix, 0.0f), (float)(TT - 1));
    float xf = floorf(xpix);
    int   x0 = (int)xf;
    int   x1 = min(x0 + 1, TT - 1);
    float wx = xpix - xf;

    // Parallel gather: threads 0-127 fetch column x0, threads 128-255 column x1.
    if (tid < FF) {
        sAD[tid].x = __ldg(S + ((size_t)b * FF + tid) * TT + x0);
    } else {
        sAD[tid - FF].y = __ldg(S + ((size_t)b * FF + (tid - FF)) * TT + x1);
    }
    __syncthreads();
    if (tid < FF) {
        float2 v = sAD[tid];
        sTmp[tid] = fmaf(wx, v.y - v.x, v.x);      // A[r] = (1-wx)*s0 + wx*s1
    }
    __syncthreads();
    if (tid < FF) {
        float a = sTmp[tid];
        sAD[tid] = make_float2(a, (tid < FF - 1) ? (sTmp[tid + 1] - a) : 0.0f);
    }
    __syncthreads();

    const float4* tab4 = (const float4*)g_yp;       // 4 j-entries per float4
    float4* orow = (float4*)(out + (size_t)row * TT);

#pragma unroll
    for (int k = 0; k < 8; k++) {
        int jg = k * 256 + tid;                     // float4 group, 0..2047
        float4 yp4 = __ldg(&tab4[jg]);

        float f0 = floorf(yp4.x);  int o0 = (int)f0;  float w0 = yp4.x - f0;
        float f1 = floorf(yp4.y);  int o1 = (int)f1;  float w1 = yp4.y - f1;
        float f2 = floorf(yp4.z);  int o2 = (int)f2;  float w2 = yp4.z - f2;
        float f3 = floorf(yp4.w);  int o3 = (int)f3;  float w3 = yp4.w - f3;

        float2 ad0 = sAD[o0];
        float2 ad1 = (o1 == o0) ? ad0 : sAD[o1];
        float2 ad2 = (o2 == o0) ? ad0 : sAD[o2];
        float2 ad3 = (o3 == o0) ? ad0 : sAD[o3];

        float4 o;
        o.x = fmaf(w0, ad0.y, ad0.x);
        o.y = fmaf(w1, ad1.y, ad1.x);
        o.z = fmaf(w2, ad2.y, ad2.x);
        o.w = fmaf(w3, ad3.y, ad3.x);
        __stcs(&orow[jg], o);
    }
}

// ---------------------------------------------------------------------------
extern "C" void kernel_launch(void* const* d_in, const int* in_sizes, int n_in,
                              void* d_out, int out_size) {
    const float* S   = (const float*)d_in[0];
    const int*   src = (const int*)d_in[1];
    const int*   dst = (const int*)d_in[2];
    float*       out = (float*)d_out;
    (void)in_sizes; (void)n_in; (void)out_size;

    k_tab<<<(TT + 255) / 256, 256>>>(src, dst);
    k_fused<<<BB * FF, 256>>>(S, out);
}